// round 14
// baseline (speedup 1.0000x reference)
#include <cuda_runtime.h>
#include <cstdint>
#include <math.h>

typedef unsigned int       u32;
typedef unsigned long long u64;

#define NPTS 4096
#define DIM  512
#define NT   528
#define NWORK 296              // persistent workers (2 CTA/SM x 148)
#define TOTN 28672.0f          // 7 * 4096 triplet terms per row

#define QS2   1.6879533717781371e-6f     // S^2, S = 0.165/127
#define QINVS 769.6969696969697f         // 1/S

#define L2E   1.4426950408889634f
#define C4C   (4.0f * L2E)
#define C40C  (40.0f * L2E)
#define K40C  2.3538526683702e17f        // e^40
#define ETH1  1.9155408290139f           // e^0.65
#define BIGF  1.0e30f
#define NBIG  (-1.9155408290139e30f)     // -ETH1 * BIGF
#define LN2   0.69314718055994531f

// ---------------- scratch ----------------------------------------------------
__device__ float g_sq[NPTS];
__device__ char  g_Xq[(size_t)NPTS * DIM];
__device__ float g_P[(size_t)NPTS * 8];      // [i][0..6]=P_k, [i][7]=pl
__device__ float g_rowS[NPTS];
__device__ float g_rowNL[NPTS];
__device__ float g_rowCnt[NPTS];
__device__ u32   g_tileCtr;
__device__ u32   g_doneCtr;

__device__ __forceinline__ float ex2f_(float x) {
    float y; asm("ex2.approx.ftz.f32 %0, %1;" : "=f"(y) : "f"(x)); return y;
}
__device__ __forceinline__ float lg2f_(float x) {
    float y; asm("lg2.approx.ftz.f32 %0, %1;" : "=f"(y) : "f"(x)); return y;
}
__device__ __forceinline__ float fmasat_(float a, float b, float c) {
    float y; asm("fma.rn.sat.f32 %0, %1, %2, %3;" : "=f"(y) : "f"(a), "f"(b), "f"(c));
    return y;
}
__device__ __forceinline__ u32 smem_u32_(const void* p) {
    u32 a;
    asm("{ .reg .u64 t; cvta.to.shared.u64 t, %1; cvt.u32.u64 %0, t; }" : "=r"(a) : "l"(p));
    return a;
}
__device__ __forceinline__ void cp_async16_(u32 dst, const void* src) {
    asm volatile("cp.async.cg.shared.global [%0], [%1], 16;"
                 :: "r"(dst), "l"(__cvta_generic_to_global(src)) : "memory");
}
template <int N>
__device__ __forceinline__ void waitg_() {
    asm volatile("cp.async.wait_group %0;" :: "n"(N) : "memory");
}

#define SW128(b) ((b) ^ (((b) >> 3) & 0x70))

#define LDX4(r, a) \
    asm volatile("ldmatrix.sync.aligned.m8n8.x4.shared.b16 {%0,%1,%2,%3}, [%4];" \
                 : "=r"((r)[0]), "=r"((r)[1]), "=r"((r)[2]), "=r"((r)[3]) : "r"(a))

#define IMMA16832(c, a, b0, b1) \
    asm volatile("mma.sync.aligned.m16n8k32.row.col.s32.s8.s8.s32 " \
                 "{%0,%1,%2,%3}, {%4,%5,%6,%7}, {%8,%9}, {%0,%1,%2,%3};" \
                 : "+r"((c)[0]), "+r"((c)[1]), "+r"((c)[2]), "+r"((c)[3]) \
                 : "r"((a)[0]), "r"((a)[1]), "r"((a)[2]), "r"((a)[3]), \
                   "r"(b0), "r"(b1))

#define TERM(PK, W, PRD, CF)                         \
    {                                                \
        float E1 = fmaf((PK), (W), 1.f);             \
        (PRD) *= fmaxf(E1, ETH1);                    \
        (CF)  += fmasat_(E1, BIGF, NBIG);            \
    }

// ---------------- K0: quantize + norms + exact pos logits -------------------
__global__ __launch_bounds__(256)
void prep_kernel(const float* __restrict__ X) {
    __shared__ float sx[8][512];
    __shared__ float ssq[8];
    __shared__ float sd[64];

    int tid  = threadIdx.x;
    int w    = tid >> 5;
    int lane = tid & 31;
    int row  = blockIdx.x * 8 + w;

    if (blockIdx.x == 0 && tid == 0) {
        g_tileCtr = NWORK; g_doneCtr = 0u;
    }
    if (tid < 8) {
        int r = blockIdx.x * 8 + tid;
        g_rowS[r] = 0.f; g_rowNL[r] = 0.f; g_rowCnt[r] = 0.f;
    }

    const float4* xr = reinterpret_cast<const float4*>(X + (size_t)row * DIM);
    char4* q4 = reinterpret_cast<char4*>(g_Xq + (size_t)row * DIM);
    float acc = 0.f;
#pragma unroll
    for (int l = 0; l < 4; l++) {
        int e4 = lane + 32 * l;
        float4 v = xr[e4];
        sx[w][e4 * 4]     = v.x; sx[w][e4 * 4 + 1] = v.y;
        sx[w][e4 * 4 + 2] = v.z; sx[w][e4 * 4 + 3] = v.w;
        acc = fmaf(v.x, v.x, acc); acc = fmaf(v.y, v.y, acc);
        acc = fmaf(v.z, v.z, acc); acc = fmaf(v.w, v.w, acc);
        float vv[4] = {v.x, v.y, v.z, v.w};
        int q[4];
#pragma unroll
        for (int u = 0; u < 4; u++) {
            float t = fminf(fmaxf(vv[u] * QINVS, -127.f), 127.f);
            q[u] = __float2int_rn(t);
        }
        q4[e4] = make_char4((char)q[0], (char)q[1], (char)q[2], (char)q[3]);
    }
#pragma unroll
    for (int o = 16; o; o >>= 1) acc += __shfl_xor_sync(0xffffffffu, acc, o);
    if (lane == 0) { g_sq[row] = acc; ssq[w] = acc; }
    __syncthreads();

    for (int pi = w; pi < 28; pi += 8) {
        int a = 0, r = pi;
        while (r >= 7 - a) { r -= 7 - a; a++; }
        int b = a + 1 + r;
        float p = 0.f;
#pragma unroll
        for (int l = 0; l < 16; l++) {
            int e = lane + 32 * l;
            p = fmaf(sx[a][e], sx[b][e], p);
        }
#pragma unroll
        for (int o = 16; o; o >>= 1) p += __shfl_xor_sync(0xffffffffu, p, o);
        if (lane == 0) {
            float d2 = ssq[a] + ssq[b] - 2.f * p;
            float d  = sqrtf(fmaxf(d2, 1e-12f));
            sd[a * 8 + b] = d; sd[b * 8 + a] = d;
        }
    }
    __syncthreads();

    if (tid < 8) {
        int r = tid;
        int rw = blockIdx.x * 8 + r;
        float pl = 0.f;
        int kidx = 0;
#pragma unroll
        for (int kk = 0; kk < 8; kk++) {
            if (kk == r) continue;
            float q = C4C * sd[r * 8 + kk];
            g_P[(size_t)rw * 8 + kidx] = ex2f_(q);
            pl += ex2f_(fmaf(-10.f, q, C40C));
            kidx++;
        }
        g_P[(size_t)rw * 8 + 7] = pl;
    }
}

// ---------------- K1: persistent fused IMMA GEMM + triplet + finalize -------
#define TILE_B 16384
#define OFF_B0   0
#define OFF_B1   32768
#define OFF_B2   65536
#define OFF_SD   0                         // float [128][129] = 66048 B
#define OFF_PI   66048
#define OFF_PJ   70144
#define OFF_SA   74240
#define OFF_SB   74752
#define DSMEM_BYTES (1024 + 3 * 32768)     // 97 KB -> 2 CTAs/SM

__device__ __forceinline__ void load_stage_(u32 buf, int k0,
                                            const char* pa, const char* pb, int tid) {
    const char* ptr[2] = {pa, pb};
#pragma unroll
    for (int tl = 0; tl < 2; tl++) {
        const char* p = ptr[tl];
#pragma unroll
        for (int i = 0; i < 2; i++) {
            int cid = tid + i * 512;
            int r   = cid >> 3;
            int g   = cid & 7;
            u32 dst = buf + tl * TILE_B + SW128(r * 128 + g * 16);
            cp_async16_(dst, p + (size_t)r * DIM + k0 + g * 16);
        }
    }
    asm volatile("cp.async.commit_group;" ::: "memory");
}

__global__ __launch_bounds__(512, 2)
void mma_triplet_kernel(float* __restrict__ out) {
    extern __shared__ char dsm[];
    u32 raw  = smem_u32_(dsm);
    u32 base = (raw + 1023) & ~1023u;
    char* ebase = dsm + (base - raw);

    __shared__ u32 sTick;
    __shared__ float sRed[2][16];

    int tid  = threadIdx.x;
    int lane = tid & 31;
    int wid  = tid >> 5;
    int m0 = (wid & 3) * 32;
    int n0 = (wid >> 2) * 32;
    int ra = (lane & 7) + ((lane >> 3) & 1) * 8;
    int cb16 = ((lane >> 4) & 1) * 16;

    float* sD  = reinterpret_cast<float*>(ebase + OFF_SD);
    float* sPi = reinterpret_cast<float*>(ebase + OFF_PI);
    float* sPj = reinterpret_cast<float*>(ebase + OFF_PJ);
    float* ssA = reinterpret_cast<float*>(ebase + OFF_SA);
    float* ssB = reinterpret_cast<float*>(ebase + OFF_SB);

    int t = blockIdx.x;

    while (t < NT) {
        int tt = t, bi = 0;
        while (tt >= 32 - bi) { tt -= 32 - bi; bi++; }
        int bj = bi + tt;
        bool diag = (bi == bj);
        const char* pa = g_Xq + (size_t)bi * 128 * DIM;
        const char* pb = g_Xq + (size_t)bj * 128 * DIM;
        const int row0 = bi * 128, col0 = bj * 128;

        int acc[2][4][4];
#pragma unroll
        for (int mt = 0; mt < 2; mt++)
#pragma unroll
            for (int nt = 0; nt < 4; nt++)
#pragma unroll
                for (int v = 0; v < 4; v++) acc[mt][nt][v] = 0;

        load_stage_(base + OFF_B0, 0,   pa, pb, tid);   // G0
        load_stage_(base + OFF_B1, 128, pa, pb, tid);   // G1
        load_stage_(base + OFF_B2, 256, pa, pb, tid);   // G2

#define COMPUTE_STAGE(SBUF)                                                  \
    {                                                                        \
        u32 bA = (SBUF), bB = (SBUF) + TILE_B;                               \
        _Pragma("unroll")                                                    \
        for (int ks = 0; ks < 4; ks++) {                                     \
            int kb = ks * 32 + cb16;                                         \
            u32 Af[2][4], Bf[2][4];                                          \
            _Pragma("unroll")                                                \
            for (int mt = 0; mt < 2; mt++) {                                 \
                int r = m0 + mt * 16 + ra;                                   \
                LDX4(Af[mt], bA + SW128(r * 128 + kb));                      \
            }                                                                \
            _Pragma("unroll")                                                \
            for (int nb = 0; nb < 2; nb++) {                                 \
                int r = n0 + nb * 16 + ra;                                   \
                LDX4(Bf[nb], bB + SW128(r * 128 + kb));                      \
            }                                                                \
            _Pragma("unroll")                                                \
            for (int mt = 0; mt < 2; mt++)                                   \
                _Pragma("unroll")                                            \
                for (int nb = 0; nb < 2; nb++)                               \
                    _Pragma("unroll")                                        \
                    for (int h = 0; h < 2; h++)                              \
                        IMMA16832(acc[mt][nb * 2 + h], Af[mt],               \
                                  Bf[nb][h], Bf[nb][2 + h]);                 \
        }                                                                    \
    }

        waitg_<2>(); __syncthreads(); COMPUTE_STAGE(base + OFF_B0);
        __syncthreads();                                 // B0 free
        load_stage_(base + OFF_B0, 384, pa, pb, tid);    // G3 -> B0
        waitg_<2>(); __syncthreads(); COMPUTE_STAGE(base + OFF_B1);
        waitg_<1>(); __syncthreads(); COMPUTE_STAGE(base + OFF_B2);
        waitg_<0>(); __syncthreads(); COMPUTE_STAGE(base + OFF_B0);
#undef COMPUTE_STAGE
        __syncthreads();

#pragma unroll
        for (int mt = 0; mt < 2; mt++)
#pragma unroll
            for (int nt = 0; nt < 4; nt++) {
                int rb = m0 + mt * 16 + (lane >> 2);
                int cbx = n0 + nt * 8 + (lane & 3) * 2;
                sD[rb * 129 + cbx]           = QS2 * (float)acc[mt][nt][0];
                sD[rb * 129 + cbx + 1]       = QS2 * (float)acc[mt][nt][1];
                sD[(rb + 8) * 129 + cbx]     = QS2 * (float)acc[mt][nt][2];
                sD[(rb + 8) * 129 + cbx + 1] = QS2 * (float)acc[mt][nt][3];
            }
        for (int idx = tid; idx < 1024; idx += 512) {
            sPi[idx] = g_P[(size_t)row0 * 8 + idx];
            sPj[idx] = g_P[(size_t)col0 * 8 + idx];
        }
        if (tid < 128) { ssA[tid] = g_sq[row0 + tid]; ssB[tid] = g_sq[col0 + tid]; }
        __syncthreads();

        // pass W
        for (int idx = tid; idx < 128 * 128; idx += 512) {
            int m = idx >> 7, c = idx & 127;
            float dot = sD[m * 129 + c];
            float d2  = ssA[m] + ssB[c] - 2.f * dot;
            float d   = sqrtf(fmaxf(d2, 1e-12f));
            float w   = ex2f_(-C4C * d);
            if (diag && ((m >> 3) == (c >> 3))) w = 0.f;
            sD[m * 129 + c] = w;
        }
        __syncthreads();

        // direction 1
        {
            int r = tid >> 2, q = tid & 3;
            float p[7];
#pragma unroll
            for (int k = 0; k < 7; k++) p[k] = sPi[r * 8 + k];
            const float* wr = sD + r * 129 + q * 32;
            int rot = 8 * q;
            float s = 0.f, nl = 0.f, cfA = 0.f, cfB = 0.f;
#pragma unroll 2
            for (int cc = 0; cc < 32; cc += 4) {
                float pA = 1.f, pB = 1.f, pC = 1.f, pD = 1.f;
#pragma unroll
                for (int u = 0; u < 4; u++) {
                    float w  = wr[(cc + u + rot) & 31];
                    float w2 = w * w, w4 = w2 * w2, w5 = w4 * w;
                    nl = fmaf(K40C, w5 * w5, nl);
                    TERM(p[0], w, pA, cfA); TERM(p[1], w, pB, cfB);
                    TERM(p[2], w, pC, cfA); TERM(p[3], w, pD, cfB);
                    TERM(p[4], w, pA, cfA); TERM(p[5], w, pB, cfB);
                    TERM(p[6], w, pC, cfA);
                }
                s += (lg2f_(pA) + lg2f_(pB)) + (lg2f_(pC) + lg2f_(pD));
            }
            float cf = cfA + cfB;
            s  += __shfl_xor_sync(0xffffffffu, s, 1);
            nl += __shfl_xor_sync(0xffffffffu, nl, 1);
            cf += __shfl_xor_sync(0xffffffffu, cf, 1);
            s  += __shfl_xor_sync(0xffffffffu, s, 2);
            nl += __shfl_xor_sync(0xffffffffu, nl, 2);
            cf += __shfl_xor_sync(0xffffffffu, cf, 2);
            if (q == 0) {
                atomicAdd(&g_rowS[row0 + r], s);
                atomicAdd(&g_rowNL[row0 + r], nl);
                atomicAdd(&g_rowCnt[row0 + r], cf);
            }
        }

        // direction 2 (off-diag only)
        if (!diag) {
            int c = tid >> 2, q = tid & 3;
            float p[7];
#pragma unroll
            for (int k = 0; k < 7; k++) p[k] = sPj[c * 8 + k];
            const float* wc = sD + c;
            int rot = 8 * q;
            float s = 0.f, nl = 0.f, cfA = 0.f, cfB = 0.f;
#pragma unroll 2
            for (int mm = 0; mm < 32; mm += 4) {
                float pA = 1.f, pB = 1.f, pC = 1.f, pD = 1.f;
#pragma unroll
                for (int u = 0; u < 4; u++) {
                    int mr = q * 32 + ((mm + u + rot) & 31);
                    float w  = wc[mr * 129];
                    float w2 = w * w, w4 = w2 * w2, w5 = w4 * w;
                    nl = fmaf(K40C, w5 * w5, nl);
                    TERM(p[0], w, pA, cfA); TERM(p[1], w, pB, cfB);
                    TERM(p[2], w, pC, cfA); TERM(p[3], w, pD, cfB);
                    TERM(p[4], w, pA, cfA); TERM(p[5], w, pB, cfB);
                    TERM(p[6], w, pC, cfA);
                }
                s += (lg2f_(pA) + lg2f_(pB)) + (lg2f_(pC) + lg2f_(pD));
            }
            float cf = cfA + cfB;
            s  += __shfl_xor_sync(0xffffffffu, s, 1);
            nl += __shfl_xor_sync(0xffffffffu, nl, 1);
            cf += __shfl_xor_sync(0xffffffffu, cf, 1);
            s  += __shfl_xor_sync(0xffffffffu, s, 2);
            nl += __shfl_xor_sync(0xffffffffu, nl, 2);
            cf += __shfl_xor_sync(0xffffffffu, cf, 2);
            if (q == 0) {
                atomicAdd(&g_rowS[col0 + c], s);
                atomicAdd(&g_rowNL[col0 + c], nl);
                atomicAdd(&g_rowCnt[col0 + c], cf);
            }
        }

        // next tile ticket; sync also fences sD reads before next loads
        if (tid == 0) sTick = atomicAdd(&g_tileCtr, 1u);
        __syncthreads();
        t = (int)sTick;
    }

    // ---- fused finalize: last CTA reduces all rows ----
    __threadfence();
    __syncthreads();
    if (tid == 0) sTick = atomicAdd(&g_doneCtr, 1u);
    __syncthreads();
    if (sTick == NWORK - 1) {
        volatile float* vS  = g_rowS;
        volatile float* vNL = g_rowNL;
        volatile float* vCF = g_rowCnt;
        float v = 0.f, cfv = 0.f;
        for (int i = tid; i < NPTS; i += 512) {
            float pl = g_P[(size_t)i * 8 + 7];
            float S  = vS[i];
            float NL = vNL[i];
            float CF = vCF[i];
            float a_lr = 1.0f - pl / (pl + NL);
            float Sln  = fmaf(LN2, S, -0.65f * (TOTN - CF));
            v   += a_lr * Sln / fmaxf(CF, 1.f);
            cfv += CF;
        }
#pragma unroll
        for (int o = 16; o; o >>= 1) {
            v   += __shfl_xor_sync(0xffffffffu, v, o);
            cfv += __shfl_xor_sync(0xffffffffu, cfv, o);
        }
        if (lane == 0) { sRed[0][wid] = v; sRed[1][wid] = cfv; }
        __syncthreads();
        if (tid == 0) {
            float V = 0.f, C = 0.f;
#pragma unroll
            for (int wq = 0; wq < 16; wq++) { V += sRed[0][wq]; C += sRed[1][wq]; }
            out[0] = (C > 0.f) ? V / C : 0.f;
        }
    }
}

// ---------------- launch ----------------------------------------------------
extern "C" void kernel_launch(void* const* d_in, const int* in_sizes, int n_in,
                              void* d_out, int out_size) {
    const float* X = (const float*)d_in[0];
    float* out = (float*)d_out;

    prep_kernel<<<NPTS / 8, 256>>>(X);

    cudaFuncSetAttribute(mma_triplet_kernel,
                         cudaFuncAttributeMaxDynamicSharedMemorySize, DSMEM_BYTES);
    mma_triplet_kernel<<<NWORK, 512, DSMEM_BYTES>>>(out);
}

// round 15
// speedup vs baseline: 1.0282x; 1.0282x over previous
#include <cuda_runtime.h>
#include <cstdint>
#include <math.h>

typedef unsigned int       u32;
typedef unsigned long long u64;

#define NPTS 4096
#define DIM  512
#define NT   528
#define TOTN 28672.0f          // 7 * 4096 triplet terms per row

#define QS2   1.6879533717781371e-6f     // S^2, S = 0.165/127
#define QINVS 769.6969696969697f         // 1/S

#define L2E   1.4426950408889634f
#define C4C   (4.0f * L2E)
#define C40C  (40.0f * L2E)
#define K40C  2.3538526683702e17f        // e^40
#define ETH1  1.9155408290139f           // e^0.65
#define BIGF  1.0e30f
#define NBIG  (-1.9155408290139e30f)     // -ETH1 * BIGF
#define LN2   0.69314718055994531f

// ---------------- scratch ----------------------------------------------------
__device__ float g_sq[NPTS];
__device__ char  g_Xq[(size_t)NPTS * DIM];
__device__ float g_P[(size_t)NPTS * 8];      // [i][0..6]=P_k, [i][7]=pl
__device__ float g_rowS[NPTS];
__device__ float g_rowNL[NPTS];
__device__ float g_rowCnt[NPTS];
__device__ u32   g_doneCtr;

__device__ __forceinline__ float ex2f_(float x) {
    float y; asm("ex2.approx.ftz.f32 %0, %1;" : "=f"(y) : "f"(x)); return y;
}
__device__ __forceinline__ float lg2f_(float x) {
    float y; asm("lg2.approx.ftz.f32 %0, %1;" : "=f"(y) : "f"(x)); return y;
}
__device__ __forceinline__ float fmasat_(float a, float b, float c) {
    float y; asm("fma.rn.sat.f32 %0, %1, %2, %3;" : "=f"(y) : "f"(a), "f"(b), "f"(c));
    return y;
}
__device__ __forceinline__ u32 smem_u32_(const void* p) {
    u32 a;
    asm("{ .reg .u64 t; cvta.to.shared.u64 t, %1; cvt.u32.u64 %0, t; }" : "=r"(a) : "l"(p));
    return a;
}
__device__ __forceinline__ void cp_async16_(u32 dst, const void* src) {
    asm volatile("cp.async.cg.shared.global [%0], [%1], 16;"
                 :: "r"(dst), "l"(__cvta_generic_to_global(src)) : "memory");
}
template <int N>
__device__ __forceinline__ void waitg_() {
    asm volatile("cp.async.wait_group %0;" :: "n"(N) : "memory");
}

#define SW128(b) ((b) ^ (((b) >> 3) & 0x70))

#define LDX4(r, a) \
    asm volatile("ldmatrix.sync.aligned.m8n8.x4.shared.b16 {%0,%1,%2,%3}, [%4];" \
                 : "=r"((r)[0]), "=r"((r)[1]), "=r"((r)[2]), "=r"((r)[3]) : "r"(a))

#define IMMA16832(c, a, b0, b1) \
    asm volatile("mma.sync.aligned.m16n8k32.row.col.s32.s8.s8.s32 " \
                 "{%0,%1,%2,%3}, {%4,%5,%6,%7}, {%8,%9}, {%0,%1,%2,%3};" \
                 : "+r"((c)[0]), "+r"((c)[1]), "+r"((c)[2]), "+r"((c)[3]) \
                 : "r"((a)[0]), "r"((a)[1]), "r"((a)[2]), "r"((a)[3]), \
                   "r"(b0), "r"(b1))

#define TERM(PK, W, PRD, CF)                         \
    {                                                \
        float E1 = fmaf((PK), (W), 1.f);             \
        (PRD) *= fmaxf(E1, ETH1);                    \
        (CF)  += fmasat_(E1, BIGF, NBIG);            \
    }

// ---------------- K0: quantize + norms + exact pos logits (4 classes/blk) ---
// 128 blocks x 1024 threads: single wave. Dynamic smem:
//   sx: 32 rows x 512 floats (64 KB), ssq: 32 floats, sd: 4 x 64 floats.
#define PREP_SMEM (32 * 512 * 4 + 32 * 4 + 4 * 64 * 4)

__global__ __launch_bounds__(1024)
void prep_kernel(const float* __restrict__ X) {
    extern __shared__ float psm[];
    float* sx  = psm;                       // [32][512]
    float* ssq = psm + 32 * 512;            // [32]
    float* sd  = ssq + 32;                  // [4][64]

    int tid  = threadIdx.x;
    int wid  = tid >> 5;                    // 0..31 (row within block)
    int lane = tid & 31;
    int cls  = wid >> 3;                    // 0..3 (class within block)
    int w8   = wid & 7;                     // row within class
    int row  = blockIdx.x * 32 + wid;

    if (blockIdx.x == 0 && tid == 0) g_doneCtr = 0u;
    if (tid < 32) {
        int r = blockIdx.x * 32 + tid;
        g_rowS[r] = 0.f; g_rowNL[r] = 0.f; g_rowCnt[r] = 0.f;
    }

    const float4* xr = reinterpret_cast<const float4*>(X + (size_t)row * DIM);
    char4* q4 = reinterpret_cast<char4*>(g_Xq + (size_t)row * DIM);
    float* sxr = sx + wid * 512;
    float acc = 0.f;
#pragma unroll
    for (int l = 0; l < 4; l++) {
        int e4 = lane + 32 * l;
        float4 v = xr[e4];
        sxr[e4 * 4]     = v.x; sxr[e4 * 4 + 1] = v.y;
        sxr[e4 * 4 + 2] = v.z; sxr[e4 * 4 + 3] = v.w;
        acc = fmaf(v.x, v.x, acc); acc = fmaf(v.y, v.y, acc);
        acc = fmaf(v.z, v.z, acc); acc = fmaf(v.w, v.w, acc);
        float vv[4] = {v.x, v.y, v.z, v.w};
        int q[4];
#pragma unroll
        for (int u = 0; u < 4; u++) {
            float t = fminf(fmaxf(vv[u] * QINVS, -127.f), 127.f);
            q[u] = __float2int_rn(t);
        }
        q4[e4] = make_char4((char)q[0], (char)q[1], (char)q[2], (char)q[3]);
    }
#pragma unroll
    for (int o = 16; o; o >>= 1) acc += __shfl_xor_sync(0xffffffffu, acc, o);
    if (lane == 0) { g_sq[row] = acc; ssq[wid] = acc; }
    __syncthreads();

    // 28 unique pairs per class, 8 warps per class
    for (int pi = w8; pi < 28; pi += 8) {
        int a = 0, r = pi;
        while (r >= 7 - a) { r -= 7 - a; a++; }
        int b = a + 1 + r;
        const float* xa = sx + (cls * 8 + a) * 512;
        const float* xb = sx + (cls * 8 + b) * 512;
        float p = 0.f;
#pragma unroll
        for (int l = 0; l < 16; l++) {
            int e = lane + 32 * l;
            p = fmaf(xa[e], xb[e], p);
        }
#pragma unroll
        for (int o = 16; o; o >>= 1) p += __shfl_xor_sync(0xffffffffu, p, o);
        if (lane == 0) {
            float d2 = ssq[cls * 8 + a] + ssq[cls * 8 + b] - 2.f * p;
            float d  = sqrtf(fmaxf(d2, 1e-12f));
            sd[cls * 64 + a * 8 + b] = d;
            sd[cls * 64 + b * 8 + a] = d;
        }
    }
    __syncthreads();

    if (tid < 32) {
        int r    = tid & 7;
        int cls2 = tid >> 3;
        int rw   = blockIdx.x * 32 + tid;
        float pl = 0.f;
        int kidx = 0;
#pragma unroll
        for (int kk = 0; kk < 8; kk++) {
            if (kk == r) continue;
            float q = C4C * sd[cls2 * 64 + r * 8 + kk];
            g_P[(size_t)rw * 8 + kidx] = ex2f_(q);
            pl += ex2f_(fmaf(-10.f, q, C40C));
            kidx++;
        }
        g_P[(size_t)rw * 8 + 7] = pl;
    }
}

// ---------------- K1: fused IMMA GEMM + triplet epilogue + tail finalize ----
#define TILE_B 16384
#define OFF_B0   0
#define OFF_B1   32768
#define OFF_B2   65536
#define OFF_SD   0                         // float [128][129] = 66048 B
#define OFF_PI   66048
#define OFF_PJ   70144
#define OFF_SA   74240
#define OFF_SB   74752
#define DSMEM_BYTES (1024 + 3 * 32768)     // 97 KB -> 2 CTAs/SM

__device__ __forceinline__ void load_stage_(u32 buf, int k0,
                                            const char* pa, const char* pb, int tid) {
    const char* ptr[2] = {pa, pb};
#pragma unroll
    for (int tl = 0; tl < 2; tl++) {
        const char* p = ptr[tl];
#pragma unroll
        for (int i = 0; i < 2; i++) {
            int cid = tid + i * 512;
            int r   = cid >> 3;
            int g   = cid & 7;
            u32 dst = buf + tl * TILE_B + SW128(r * 128 + g * 16);
            cp_async16_(dst, p + (size_t)r * DIM + k0 + g * 16);
        }
    }
    asm volatile("cp.async.commit_group;" ::: "memory");
}

__global__ __launch_bounds__(512, 2)
void mma_triplet_kernel(float* __restrict__ out) {
    extern __shared__ char dsm[];
    u32 raw  = smem_u32_(dsm);
    u32 base = (raw + 1023) & ~1023u;
    char* ebase = dsm + (base - raw);

    __shared__ u32 sTick;
    __shared__ float sRed[2][16];

    int t = blockIdx.x, bi = 0;
    while (t >= 32 - bi) { t -= 32 - bi; bi++; }
    int bj = bi + t;
    bool diag = (bi == bj);
    int tid  = threadIdx.x;
    int lane = tid & 31;
    int wid  = tid >> 5;
    int m0 = (wid & 3) * 32;
    int n0 = (wid >> 2) * 32;
    int ra = (lane & 7) + ((lane >> 3) & 1) * 8;
    int cb16 = ((lane >> 4) & 1) * 16;

    const char* pa = g_Xq + (size_t)bi * 128 * DIM;
    const char* pb = g_Xq + (size_t)bj * 128 * DIM;

    int acc[2][4][4];
#pragma unroll
    for (int mt = 0; mt < 2; mt++)
#pragma unroll
        for (int nt = 0; nt < 4; nt++)
#pragma unroll
            for (int v = 0; v < 4; v++) acc[mt][nt][v] = 0;

    load_stage_(base + OFF_B0, 0,   pa, pb, tid);   // G0
    load_stage_(base + OFF_B1, 128, pa, pb, tid);   // G1
    load_stage_(base + OFF_B2, 256, pa, pb, tid);   // G2

#define COMPUTE_STAGE(SBUF)                                                  \
    {                                                                        \
        u32 bA = (SBUF), bB = (SBUF) + TILE_B;                               \
        _Pragma("unroll")                                                    \
        for (int ks = 0; ks < 4; ks++) {                                     \
            int kb = ks * 32 + cb16;                                         \
            u32 Af[2][4], Bf[2][4];                                          \
            _Pragma("unroll")                                                \
            for (int mt = 0; mt < 2; mt++) {                                 \
                int r = m0 + mt * 16 + ra;                                   \
                LDX4(Af[mt], bA + SW128(r * 128 + kb));                      \
            }                                                                \
            _Pragma("unroll")                                                \
            for (int nb = 0; nb < 2; nb++) {                                 \
                int r = n0 + nb * 16 + ra;                                   \
                LDX4(Bf[nb], bB + SW128(r * 128 + kb));                      \
            }                                                                \
            _Pragma("unroll")                                                \
            for (int mt = 0; mt < 2; mt++)                                   \
                _Pragma("unroll")                                            \
                for (int nb = 0; nb < 2; nb++)                               \
                    _Pragma("unroll")                                        \
                    for (int h = 0; h < 2; h++)                              \
                        IMMA16832(acc[mt][nb * 2 + h], Af[mt],               \
                                  Bf[nb][h], Bf[nb][2 + h]);                 \
        }                                                                    \
    }

    waitg_<2>(); __syncthreads(); COMPUTE_STAGE(base + OFF_B0);
    __syncthreads();                                 // B0 free
    load_stage_(base + OFF_B0, 384, pa, pb, tid);    // G3 -> B0
    waitg_<2>(); __syncthreads(); COMPUTE_STAGE(base + OFF_B1);
    waitg_<1>(); __syncthreads(); COMPUTE_STAGE(base + OFF_B2);
    waitg_<0>(); __syncthreads(); COMPUTE_STAGE(base + OFF_B0);
#undef COMPUTE_STAGE
    __syncthreads();

    float* sD  = reinterpret_cast<float*>(ebase + OFF_SD);
    float* sPi = reinterpret_cast<float*>(ebase + OFF_PI);
    float* sPj = reinterpret_cast<float*>(ebase + OFF_PJ);
    float* ssA = reinterpret_cast<float*>(ebase + OFF_SA);
    float* ssB = reinterpret_cast<float*>(ebase + OFF_SB);
    const int row0 = bi * 128, col0 = bj * 128;

#pragma unroll
    for (int mt = 0; mt < 2; mt++)
#pragma unroll
        for (int nt = 0; nt < 4; nt++) {
            int rb = m0 + mt * 16 + (lane >> 2);
            int cbx = n0 + nt * 8 + (lane & 3) * 2;
            sD[rb * 129 + cbx]           = QS2 * (float)acc[mt][nt][0];
            sD[rb * 129 + cbx + 1]       = QS2 * (float)acc[mt][nt][1];
            sD[(rb + 8) * 129 + cbx]     = QS2 * (float)acc[mt][nt][2];
            sD[(rb + 8) * 129 + cbx + 1] = QS2 * (float)acc[mt][nt][3];
        }
    for (int idx = tid; idx < 1024; idx += 512) {
        sPi[idx] = g_P[(size_t)row0 * 8 + idx];
        sPj[idx] = g_P[(size_t)col0 * 8 + idx];
    }
    if (tid < 128) { ssA[tid] = g_sq[row0 + tid]; ssB[tid] = g_sq[col0 + tid]; }
    __syncthreads();

    // pass W
    for (int idx = tid; idx < 128 * 128; idx += 512) {
        int m = idx >> 7, c = idx & 127;
        float dot = sD[m * 129 + c];
        float d2  = ssA[m] + ssB[c] - 2.f * dot;
        float d   = sqrtf(fmaxf(d2, 1e-12f));
        float w   = ex2f_(-C4C * d);
        if (diag && ((m >> 3) == (c >> 3))) w = 0.f;
        sD[m * 129 + c] = w;
    }
    __syncthreads();

    // direction 1
    {
        int r = tid >> 2, q = tid & 3;
        float p[7];
#pragma unroll
        for (int k = 0; k < 7; k++) p[k] = sPi[r * 8 + k];
        const float* wr = sD + r * 129 + q * 32;
        int rot = 8 * q;
        float s = 0.f, nl = 0.f, cfA = 0.f, cfB = 0.f;
#pragma unroll 2
        for (int cc = 0; cc < 32; cc += 4) {
            float pA = 1.f, pB = 1.f, pC = 1.f, pD = 1.f;
#pragma unroll
            for (int u = 0; u < 4; u++) {
                float w  = wr[(cc + u + rot) & 31];
                float w2 = w * w, w4 = w2 * w2, w5 = w4 * w;
                nl = fmaf(K40C, w5 * w5, nl);
                TERM(p[0], w, pA, cfA); TERM(p[1], w, pB, cfB);
                TERM(p[2], w, pC, cfA); TERM(p[3], w, pD, cfB);
                TERM(p[4], w, pA, cfA); TERM(p[5], w, pB, cfB);
                TERM(p[6], w, pC, cfA);
            }
            s += (lg2f_(pA) + lg2f_(pB)) + (lg2f_(pC) + lg2f_(pD));
        }
        float cf = cfA + cfB;
        s  += __shfl_xor_sync(0xffffffffu, s, 1);
        nl += __shfl_xor_sync(0xffffffffu, nl, 1);
        cf += __shfl_xor_sync(0xffffffffu, cf, 1);
        s  += __shfl_xor_sync(0xffffffffu, s, 2);
        nl += __shfl_xor_sync(0xffffffffu, nl, 2);
        cf += __shfl_xor_sync(0xffffffffu, cf, 2);
        if (q == 0) {
            atomicAdd(&g_rowS[row0 + r], s);
            atomicAdd(&g_rowNL[row0 + r], nl);
            atomicAdd(&g_rowCnt[row0 + r], cf);
        }
    }

    // direction 2 (off-diag only)
    if (!diag) {
        int c = tid >> 2, q = tid & 3;
        float p[7];
#pragma unroll
        for (int k = 0; k < 7; k++) p[k] = sPj[c * 8 + k];
        const float* wc = sD + c;
        int rot = 8 * q;
        float s = 0.f, nl = 0.f, cfA = 0.f, cfB = 0.f;
#pragma unroll 2
        for (int mm = 0; mm < 32; mm += 4) {
            float pA = 1.f, pB = 1.f, pC = 1.f, pD = 1.f;
#pragma unroll
            for (int u = 0; u < 4; u++) {
                int mr = q * 32 + ((mm + u + rot) & 31);
                float w  = wc[mr * 129];
                float w2 = w * w, w4 = w2 * w2, w5 = w4 * w;
                nl = fmaf(K40C, w5 * w5, nl);
                TERM(p[0], w, pA, cfA); TERM(p[1], w, pB, cfB);
                TERM(p[2], w, pC, cfA); TERM(p[3], w, pD, cfB);
                TERM(p[4], w, pA, cfA); TERM(p[5], w, pB, cfB);
                TERM(p[6], w, pC, cfA);
            }
            s += (lg2f_(pA) + lg2f_(pB)) + (lg2f_(pC) + lg2f_(pD));
        }
        float cf = cfA + cfB;
        s  += __shfl_xor_sync(0xffffffffu, s, 1);
        nl += __shfl_xor_sync(0xffffffffu, nl, 1);
        cf += __shfl_xor_sync(0xffffffffu, cf, 1);
        s  += __shfl_xor_sync(0xffffffffu, s, 2);
        nl += __shfl_xor_sync(0xffffffffu, nl, 2);
        cf += __shfl_xor_sync(0xffffffffu, cf, 2);
        if (q == 0) {
            atomicAdd(&g_rowS[col0 + c], s);
            atomicAdd(&g_rowNL[col0 + c], nl);
            atomicAdd(&g_rowCnt[col0 + c], cf);
        }
    }

    // ---- tail finalize: last CTA to finish reduces all rows ----
    __threadfence();
    __syncthreads();
    if (tid == 0) sTick = atomicAdd(&g_doneCtr, 1u);
    __syncthreads();
    if (sTick == NT - 1) {
        volatile float* vS  = g_rowS;
        volatile float* vNL = g_rowNL;
        volatile float* vCF = g_rowCnt;
        float v = 0.f, cfv = 0.f;
        for (int i = tid; i < NPTS; i += 512) {
            float pl = g_P[(size_t)i * 8 + 7];
            float S  = vS[i];
            float NL = vNL[i];
            float CF = vCF[i];
            float a_lr = 1.0f - pl / (pl + NL);
            float Sln  = fmaf(LN2, S, -0.65f * (TOTN - CF));
            v   += a_lr * Sln / fmaxf(CF, 1.f);
            cfv += CF;
        }
#pragma unroll
        for (int o = 16; o; o >>= 1) {
            v   += __shfl_xor_sync(0xffffffffu, v, o);
            cfv += __shfl_xor_sync(0xffffffffu, cfv, o);
        }
        if (lane == 0) { sRed[0][wid] = v; sRed[1][wid] = cfv; }
        __syncthreads();
        if (tid == 0) {
            float V = 0.f, C = 0.f;
#pragma unroll
            for (int wq = 0; wq < 16; wq++) { V += sRed[0][wq]; C += sRed[1][wq]; }
            out[0] = (C > 0.f) ? V / C : 0.f;
        }
    }
}

// ---------------- launch ----------------------------------------------------
extern "C" void kernel_launch(void* const* d_in, const int* in_sizes, int n_in,
                              void* d_out, int out_size) {
    const float* X = (const float*)d_in[0];
    float* out = (float*)d_out;

    cudaFuncSetAttribute(prep_kernel,
                         cudaFuncAttributeMaxDynamicSharedMemorySize, PREP_SMEM);
    prep_kernel<<<NPTS / 32, 1024, PREP_SMEM>>>(X);

    cudaFuncSetAttribute(mma_triplet_kernel,
                         cudaFuncAttributeMaxDynamicSharedMemorySize, DSMEM_BYTES);
    mma_triplet_kernel<<<NT, 512, DSMEM_BYTES>>>(out);
}

// round 16
// speedup vs baseline: 1.0291x; 1.0009x over previous
#include <cuda_runtime.h>
#include <cstdint>
#include <math.h>

typedef unsigned int       u32;
typedef unsigned long long u64;

#define NPTS 4096
#define DIM  512
#define NT   528
#define TOTN 28672.0f          // 7 * 4096 triplet terms per row

#define QS2   1.6879533717781371e-6f     // S^2, S = 0.165/127
#define QINVS 769.6969696969697f         // 1/S

#define L2E   1.4426950408889634f
#define C4C   (4.0f * L2E)
#define C40C  (40.0f * L2E)
#define K40C  2.3538526683702e17f        // e^40
#define ETH1  1.9155408290139f           // e^0.65
#define BIGF  1.0e30f
#define NBIG  (-1.9155408290139e30f)     // -ETH1 * BIGF
#define LN2   0.69314718055994531f

// ---------------- scratch ----------------------------------------------------
__device__ float g_sq[NPTS];
__device__ char  g_Xq[(size_t)NPTS * DIM];
__device__ float g_P[(size_t)NPTS * 8];      // [i][0..6]=P_k, [i][7]=pl
__device__ float g_rowS[NPTS];
__device__ float g_rowNL[NPTS];
__device__ float g_rowCnt[NPTS];
__device__ u32   g_doneCtr;

__device__ __forceinline__ float ex2f_(float x) {
    float y; asm("ex2.approx.ftz.f32 %0, %1;" : "=f"(y) : "f"(x)); return y;
}
__device__ __forceinline__ float lg2f_(float x) {
    float y; asm("lg2.approx.ftz.f32 %0, %1;" : "=f"(y) : "f"(x)); return y;
}
__device__ __forceinline__ float fmasat_(float a, float b, float c) {
    float y; asm("fma.rn.sat.f32 %0, %1, %2, %3;" : "=f"(y) : "f"(a), "f"(b), "f"(c));
    return y;
}
__device__ __forceinline__ u32 smem_u32_(const void* p) {
    u32 a;
    asm("{ .reg .u64 t; cvta.to.shared.u64 t, %1; cvt.u32.u64 %0, t; }" : "=r"(a) : "l"(p));
    return a;
}
__device__ __forceinline__ void cp_async16_(u32 dst, const void* src) {
    asm volatile("cp.async.cg.shared.global [%0], [%1], 16;"
                 :: "r"(dst), "l"(__cvta_generic_to_global(src)) : "memory");
}
template <int N>
__device__ __forceinline__ void waitg_() {
    asm volatile("cp.async.wait_group %0;" :: "n"(N) : "memory");
}

#define SW128(b) ((b) ^ (((b) >> 3) & 0x70))

#define LDX4(r, a) \
    asm volatile("ldmatrix.sync.aligned.m8n8.x4.shared.b16 {%0,%1,%2,%3}, [%4];" \
                 : "=r"((r)[0]), "=r"((r)[1]), "=r"((r)[2]), "=r"((r)[3]) : "r"(a))

#define IMMA16832(c, a, b0, b1) \
    asm volatile("mma.sync.aligned.m16n8k32.row.col.s32.s8.s8.s32 " \
                 "{%0,%1,%2,%3}, {%4,%5,%6,%7}, {%8,%9}, {%0,%1,%2,%3};" \
                 : "+r"((c)[0]), "+r"((c)[1]), "+r"((c)[2]), "+r"((c)[3]) \
                 : "r"((a)[0]), "r"((a)[1]), "r"((a)[2]), "r"((a)[3]), \
                   "r"(b0), "r"(b1))

#define TERM(PK, W, PRD, CF)                         \
    {                                                \
        float E1 = fmaf((PK), (W), 1.f);             \
        (PRD) *= fmaxf(E1, ETH1);                    \
        (CF)  += fmasat_(E1, BIGF, NBIG);            \
    }

// ---------------- K0: quantize + norms + exact pos logits (4 classes/blk) ---
// 128 blocks x 1024 threads: single wave. Dynamic smem:
//   sx: 32 rows x 512 floats (64 KB), ssq: 32 floats, sd: 4 x 64 floats.
#define PREP_SMEM (32 * 512 * 4 + 32 * 4 + 4 * 64 * 4)

__global__ __launch_bounds__(1024)
void prep_kernel(const float* __restrict__ X) {
    extern __shared__ float psm[];
    float* sx  = psm;                       // [32][512]
    float* ssq = psm + 32 * 512;            // [32]
    float* sd  = ssq + 32;                  // [4][64]

    int tid  = threadIdx.x;
    int wid  = tid >> 5;                    // 0..31 (row within block)
    int lane = tid & 31;
    int cls  = wid >> 3;                    // 0..3 (class within block)
    int w8   = wid & 7;                     // row within class
    int row  = blockIdx.x * 32 + wid;

    if (blockIdx.x == 0 && tid == 0) g_doneCtr = 0u;
    if (tid < 32) {
        int r = blockIdx.x * 32 + tid;
        g_rowS[r] = 0.f; g_rowNL[r] = 0.f; g_rowCnt[r] = 0.f;
    }

    const float4* xr = reinterpret_cast<const float4*>(X + (size_t)row * DIM);
    char4* q4 = reinterpret_cast<char4*>(g_Xq + (size_t)row * DIM);
    float* sxr = sx + wid * 512;
    float acc = 0.f;
#pragma unroll
    for (int l = 0; l < 4; l++) {
        int e4 = lane + 32 * l;
        float4 v = xr[e4];
        sxr[e4 * 4]     = v.x; sxr[e4 * 4 + 1] = v.y;
        sxr[e4 * 4 + 2] = v.z; sxr[e4 * 4 + 3] = v.w;
        acc = fmaf(v.x, v.x, acc); acc = fmaf(v.y, v.y, acc);
        acc = fmaf(v.z, v.z, acc); acc = fmaf(v.w, v.w, acc);
        float vv[4] = {v.x, v.y, v.z, v.w};
        int q[4];
#pragma unroll
        for (int u = 0; u < 4; u++) {
            float t = fminf(fmaxf(vv[u] * QINVS, -127.f), 127.f);
            q[u] = __float2int_rn(t);
        }
        q4[e4] = make_char4((char)q[0], (char)q[1], (char)q[2], (char)q[3]);
    }
#pragma unroll
    for (int o = 16; o; o >>= 1) acc += __shfl_xor_sync(0xffffffffu, acc, o);
    if (lane == 0) { g_sq[row] = acc; ssq[wid] = acc; }
    __syncthreads();

    // 28 unique pairs per class, 8 warps per class
    for (int pi = w8; pi < 28; pi += 8) {
        int a = 0, r = pi;
        while (r >= 7 - a) { r -= 7 - a; a++; }
        int b = a + 1 + r;
        const float* xa = sx + (cls * 8 + a) * 512;
        const float* xb = sx + (cls * 8 + b) * 512;
        float p = 0.f;
#pragma unroll
        for (int l = 0; l < 16; l++) {
            int e = lane + 32 * l;
            p = fmaf(xa[e], xb[e], p);
        }
#pragma unroll
        for (int o = 16; o; o >>= 1) p += __shfl_xor_sync(0xffffffffu, p, o);
        if (lane == 0) {
            float d2 = ssq[cls * 8 + a] + ssq[cls * 8 + b] - 2.f * p;
            float d  = sqrtf(fmaxf(d2, 1e-12f));
            sd[cls * 64 + a * 8 + b] = d;
            sd[cls * 64 + b * 8 + a] = d;
        }
    }
    __syncthreads();

    if (tid < 32) {
        int r    = tid & 7;
        int cls2 = tid >> 3;
        int rw   = blockIdx.x * 32 + tid;
        float pl = 0.f;
        int kidx = 0;
#pragma unroll
        for (int kk = 0; kk < 8; kk++) {
            if (kk == r) continue;
            float q = C4C * sd[cls2 * 64 + r * 8 + kk];
            g_P[(size_t)rw * 8 + kidx] = ex2f_(q);
            pl += ex2f_(fmaf(-10.f, q, C40C));
            kidx++;
        }
        g_P[(size_t)rw * 8 + 7] = pl;
    }
}

// ---------------- K1: fused IMMA GEMM + triplet epilogue + tail finalize ----
#define TILE_B 16384
#define OFF_B0   0
#define OFF_B1   32768
#define OFF_B2   65536
#define OFF_SD   0                         // float [128][129] = 66048 B
#define OFF_PI   66048
#define OFF_PJ   70144
#define OFF_SA   74240
#define OFF_SB   74752
#define DSMEM_BYTES (1024 + 3 * 32768)     // 97 KB -> 2 CTAs/SM

__device__ __forceinline__ void load_stage_(u32 buf, int k0,
                                            const char* pa, const char* pb, int tid) {
    const char* ptr[2] = {pa, pb};
#pragma unroll
    for (int tl = 0; tl < 2; tl++) {
        const char* p = ptr[tl];
#pragma unroll
        for (int i = 0; i < 2; i++) {
            int cid = tid + i * 512;
            int r   = cid >> 3;
            int g   = cid & 7;
            u32 dst = buf + tl * TILE_B + SW128(r * 128 + g * 16);
            cp_async16_(dst, p + (size_t)r * DIM + k0 + g * 16);
        }
    }
    asm volatile("cp.async.commit_group;" ::: "memory");
}

__global__ __launch_bounds__(512, 2)
void mma_triplet_kernel(float* __restrict__ out) {
    extern __shared__ char dsm[];
    u32 raw  = smem_u32_(dsm);
    u32 base = (raw + 1023) & ~1023u;
    char* ebase = dsm + (base - raw);

    __shared__ u32 sTick;
    __shared__ float sRed[2][16];

    int t = blockIdx.x, bi = 0;
    while (t >= 32 - bi) { t -= 32 - bi; bi++; }
    int bj = bi + t;
    bool diag = (bi == bj);
    int tid  = threadIdx.x;
    int lane = tid & 31;
    int wid  = tid >> 5;
    int m0 = (wid & 3) * 32;
    int n0 = (wid >> 2) * 32;
    int ra = (lane & 7) + ((lane >> 3) & 1) * 8;
    int cb16 = ((lane >> 4) & 1) * 16;

    const char* pa = g_Xq + (size_t)bi * 128 * DIM;
    const char* pb = g_Xq + (size_t)bj * 128 * DIM;

    int acc[2][4][4];
#pragma unroll
    for (int mt = 0; mt < 2; mt++)
#pragma unroll
        for (int nt = 0; nt < 4; nt++)
#pragma unroll
            for (int v = 0; v < 4; v++) acc[mt][nt][v] = 0;

    load_stage_(base + OFF_B0, 0,   pa, pb, tid);   // G0
    load_stage_(base + OFF_B1, 128, pa, pb, tid);   // G1
    load_stage_(base + OFF_B2, 256, pa, pb, tid);   // G2

#define COMPUTE_STAGE(SBUF)                                                  \
    {                                                                        \
        u32 bA = (SBUF), bB = (SBUF) + TILE_B;                               \
        _Pragma("unroll")                                                    \
        for (int ks = 0; ks < 4; ks++) {                                     \
            int kb = ks * 32 + cb16;                                         \
            u32 Af[2][4], Bf[2][4];                                          \
            _Pragma("unroll")                                                \
            for (int mt = 0; mt < 2; mt++) {                                 \
                int r = m0 + mt * 16 + ra;                                   \
                LDX4(Af[mt], bA + SW128(r * 128 + kb));                      \
            }                                                                \
            _Pragma("unroll")                                                \
            for (int nb = 0; nb < 2; nb++) {                                 \
                int r = n0 + nb * 16 + ra;                                   \
                LDX4(Bf[nb], bB + SW128(r * 128 + kb));                      \
            }                                                                \
            _Pragma("unroll")                                                \
            for (int mt = 0; mt < 2; mt++)                                   \
                _Pragma("unroll")                                            \
                for (int nb = 0; nb < 2; nb++)                               \
                    _Pragma("unroll")                                        \
                    for (int h = 0; h < 2; h++)                              \
                        IMMA16832(acc[mt][nb * 2 + h], Af[mt],               \
                                  Bf[nb][h], Bf[nb][2 + h]);                 \
        }                                                                    \
    }

    waitg_<2>(); __syncthreads(); COMPUTE_STAGE(base + OFF_B0);
    __syncthreads();                                 // B0 free
    load_stage_(base + OFF_B0, 384, pa, pb, tid);    // G3 -> B0
    waitg_<2>(); __syncthreads(); COMPUTE_STAGE(base + OFF_B1);
    waitg_<1>(); __syncthreads(); COMPUTE_STAGE(base + OFF_B2);
    waitg_<0>(); __syncthreads(); COMPUTE_STAGE(base + OFF_B0);
#undef COMPUTE_STAGE
    __syncthreads();

    float* sD  = reinterpret_cast<float*>(ebase + OFF_SD);
    float* sPi = reinterpret_cast<float*>(ebase + OFF_PI);
    float* sPj = reinterpret_cast<float*>(ebase + OFF_PJ);
    float* ssA = reinterpret_cast<float*>(ebase + OFF_SA);
    float* ssB = reinterpret_cast<float*>(ebase + OFF_SB);
    const int row0 = bi * 128, col0 = bj * 128;

#pragma unroll
    for (int mt = 0; mt < 2; mt++)
#pragma unroll
        for (int nt = 0; nt < 4; nt++) {
            int rb = m0 + mt * 16 + (lane >> 2);
            int cbx = n0 + nt * 8 + (lane & 3) * 2;
            sD[rb * 129 + cbx]           = QS2 * (float)acc[mt][nt][0];
            sD[rb * 129 + cbx + 1]       = QS2 * (float)acc[mt][nt][1];
            sD[(rb + 8) * 129 + cbx]     = QS2 * (float)acc[mt][nt][2];
            sD[(rb + 8) * 129 + cbx + 1] = QS2 * (float)acc[mt][nt][3];
        }
    for (int idx = tid; idx < 1024; idx += 512) {
        sPi[idx] = g_P[(size_t)row0 * 8 + idx];
        sPj[idx] = g_P[(size_t)col0 * 8 + idx];
    }
    if (tid < 128) { ssA[tid] = g_sq[row0 + tid]; ssB[tid] = g_sq[col0 + tid]; }
    __syncthreads();

    // pass W
    for (int idx = tid; idx < 128 * 128; idx += 512) {
        int m = idx >> 7, c = idx & 127;
        float dot = sD[m * 129 + c];
        float d2  = ssA[m] + ssB[c] - 2.f * dot;
        float d   = sqrtf(fmaxf(d2, 1e-12f));
        float w   = ex2f_(-C4C * d);
        if (diag && ((m >> 3) == (c >> 3))) w = 0.f;
        sD[m * 129 + c] = w;
    }
    __syncthreads();

    // direction 1
    {
        int r = tid >> 2, q = tid & 3;
        float p[7];
#pragma unroll
        for (int k = 0; k < 7; k++) p[k] = sPi[r * 8 + k];
        const float* wr = sD + r * 129 + q * 32;
        int rot = 8 * q;
        float s = 0.f, nl = 0.f, cfA = 0.f, cfB = 0.f;
#pragma unroll 2
        for (int cc = 0; cc < 32; cc += 4) {
            float pA = 1.f, pB = 1.f, pC = 1.f, pD = 1.f;
#pragma unroll
            for (int u = 0; u < 4; u++) {
                float w  = wr[(cc + u + rot) & 31];
                float w2 = w * w, w4 = w2 * w2, w5 = w4 * w;
                nl = fmaf(K40C, w5 * w5, nl);
                TERM(p[0], w, pA, cfA); TERM(p[1], w, pB, cfB);
                TERM(p[2], w, pC, cfA); TERM(p[3], w, pD, cfB);
                TERM(p[4], w, pA, cfA); TERM(p[5], w, pB, cfB);
                TERM(p[6], w, pC, cfA);
            }
            s += (lg2f_(pA) + lg2f_(pB)) + (lg2f_(pC) + lg2f_(pD));
        }
        float cf = cfA + cfB;
        s  += __shfl_xor_sync(0xffffffffu, s, 1);
        nl += __shfl_xor_sync(0xffffffffu, nl, 1);
        cf += __shfl_xor_sync(0xffffffffu, cf, 1);
        s  += __shfl_xor_sync(0xffffffffu, s, 2);
        nl += __shfl_xor_sync(0xffffffffu, nl, 2);
        cf += __shfl_xor_sync(0xffffffffu, cf, 2);
        if (q == 0) {
            atomicAdd(&g_rowS[row0 + r], s);
            atomicAdd(&g_rowNL[row0 + r], nl);
            atomicAdd(&g_rowCnt[row0 + r], cf);
        }
    }

    // direction 2 (off-diag only)
    if (!diag) {
        int c = tid >> 2, q = tid & 3;
        float p[7];
#pragma unroll
        for (int k = 0; k < 7; k++) p[k] = sPj[c * 8 + k];
        const float* wc = sD + c;
        int rot = 8 * q;
        float s = 0.f, nl = 0.f, cfA = 0.f, cfB = 0.f;
#pragma unroll 2
        for (int mm = 0; mm < 32; mm += 4) {
            float pA = 1.f, pB = 1.f, pC = 1.f, pD = 1.f;
#pragma unroll
            for (int u = 0; u < 4; u++) {
                int mr = q * 32 + ((mm + u + rot) & 31);
                float w  = wc[mr * 129];
                float w2 = w * w, w4 = w2 * w2, w5 = w4 * w;
                nl = fmaf(K40C, w5 * w5, nl);
                TERM(p[0], w, pA, cfA); TERM(p[1], w, pB, cfB);
                TERM(p[2], w, pC, cfA); TERM(p[3], w, pD, cfB);
                TERM(p[4], w, pA, cfA); TERM(p[5], w, pB, cfB);
                TERM(p[6], w, pC, cfA);
            }
            s += (lg2f_(pA) + lg2f_(pB)) + (lg2f_(pC) + lg2f_(pD));
        }
        float cf = cfA + cfB;
        s  += __shfl_xor_sync(0xffffffffu, s, 1);
        nl += __shfl_xor_sync(0xffffffffu, nl, 1);
        cf += __shfl_xor_sync(0xffffffffu, cf, 1);
        s  += __shfl_xor_sync(0xffffffffu, s, 2);
        nl += __shfl_xor_sync(0xffffffffu, nl, 2);
        cf += __shfl_xor_sync(0xffffffffu, cf, 2);
        if (q == 0) {
            atomicAdd(&g_rowS[col0 + c], s);
            atomicAdd(&g_rowNL[col0 + c], nl);
            atomicAdd(&g_rowCnt[col0 + c], cf);
        }
    }

    // ---- tail finalize: last CTA to finish reduces all rows ----
    __threadfence();
    __syncthreads();
    if (tid == 0) sTick = atomicAdd(&g_doneCtr, 1u);
    __syncthreads();
    if (sTick == NT - 1) {
        volatile float* vS  = g_rowS;
        volatile float* vNL = g_rowNL;
        volatile float* vCF = g_rowCnt;
        float v = 0.f, cfv = 0.f;
        for (int i = tid; i < NPTS; i += 512) {
            float pl = g_P[(size_t)i * 8 + 7];
            float S  = vS[i];
            float NL = vNL[i];
            float CF = vCF[i];
            float a_lr = 1.0f - pl / (pl + NL);
            float Sln  = fmaf(LN2, S, -0.65f * (TOTN - CF));
            v   += a_lr * Sln / fmaxf(CF, 1.f);
            cfv += CF;
        }
#pragma unroll
        for (int o = 16; o; o >>= 1) {
            v   += __shfl_xor_sync(0xffffffffu, v, o);
            cfv += __shfl_xor_sync(0xffffffffu, cfv, o);
        }
        if (lane == 0) { sRed[0][wid] = v; sRed[1][wid] = cfv; }
        __syncthreads();
        if (tid == 0) {
            float V = 0.f, C = 0.f;
#pragma unroll
            for (int wq = 0; wq < 16; wq++) { V += sRed[0][wq]; C += sRed[1][wq]; }
            out[0] = (C > 0.f) ? V / C : 0.f;
        }
    }
}

// ---------------- launch ----------------------------------------------------
extern "C" void kernel_launch(void* const* d_in, const int* in_sizes, int n_in,
                              void* d_out, int out_size) {
    const float* X = (const float*)d_in[0];
    float* out = (float*)d_out;

    cudaFuncSetAttribute(prep_kernel,
                         cudaFuncAttributeMaxDynamicSharedMemorySize, PREP_SMEM);
    prep_kernel<<<NPTS / 32, 1024, PREP_SMEM>>>(X);

    cudaFuncSetAttribute(mma_triplet_kernel,
                         cudaFuncAttributeMaxDynamicSharedMemorySize, DSMEM_BYTES);
    mma_triplet_kernel<<<NT, 512, DSMEM_BYTES>>>(out);
}

// round 17
// speedup vs baseline: 1.0882x; 1.0574x over previous
#include <cuda_runtime.h>
#include <cstdint>
#include <math.h>

typedef unsigned int       u32;
typedef unsigned long long u64;

#define NPTS 4096
#define DIM  512
#define NT   528
#define TOTN 28672.0f          // 7 * 4096 triplet terms per row

#define QS2   1.6879533717781371e-6f     // S^2, S = 0.165/127
#define QINVS 769.6969696969697f         // 1/S

#define L2E   1.4426950408889634f
#define C4C   (4.0f * L2E)
#define C40C  (40.0f * L2E)
#define K40C  2.3538526683702e17f        // e^40
#define ETH1  1.9155408290139f           // e^0.65
#define BIGF  1.0e30f
#define NBIG  (-1.9155408290139e30f)     // -ETH1 * BIGF
#define LN2   0.69314718055994531f

// ---------------- scratch ----------------------------------------------------
__device__ float g_sq[NPTS];
__device__ char  g_Xq[(size_t)NPTS * DIM];
__device__ float g_P[(size_t)NPTS * 8];      // [i][0..6]=P_k, [i][7]=pl
__device__ float g_rowS[NPTS];
__device__ float g_rowNL[NPTS];
__device__ float g_rowCnt[NPTS];
__device__ float g_sumLoss;
__device__ float g_cntTot;
__device__ u32   g_ticket;

__device__ __forceinline__ float ex2f_(float x) {
    float y; asm("ex2.approx.ftz.f32 %0, %1;" : "=f"(y) : "f"(x)); return y;
}
__device__ __forceinline__ float lg2f_(float x) {
    float y; asm("lg2.approx.ftz.f32 %0, %1;" : "=f"(y) : "f"(x)); return y;
}
__device__ __forceinline__ float fmasat_(float a, float b, float c) {
    float y; asm("fma.rn.sat.f32 %0, %1, %2, %3;" : "=f"(y) : "f"(a), "f"(b), "f"(c));
    return y;
}
__device__ __forceinline__ u32 smem_u32_(const void* p) {
    u32 a;
    asm("{ .reg .u64 t; cvta.to.shared.u64 t, %1; cvt.u32.u64 %0, t; }" : "=r"(a) : "l"(p));
    return a;
}
__device__ __forceinline__ void cp_async16_(u32 dst, const void* src) {
    asm volatile("cp.async.cg.shared.global [%0], [%1], 16;"
                 :: "r"(dst), "l"(__cvta_generic_to_global(src)) : "memory");
}
template <int N>
__device__ __forceinline__ void waitg_() {
    asm volatile("cp.async.wait_group %0;" :: "n"(N) : "memory");
}

#define SW128(b) ((b) ^ (((b) >> 3) & 0x70))

#define LDX4(r, a) \
    asm volatile("ldmatrix.sync.aligned.m8n8.x4.shared.b16 {%0,%1,%2,%3}, [%4];" \
                 : "=r"((r)[0]), "=r"((r)[1]), "=r"((r)[2]), "=r"((r)[3]) : "r"(a))

#define IMMA16832(c, a, b0, b1) \
    asm volatile("mma.sync.aligned.m16n8k32.row.col.s32.s8.s8.s32 " \
                 "{%0,%1,%2,%3}, {%4,%5,%6,%7}, {%8,%9}, {%0,%1,%2,%3};" \
                 : "+r"((c)[0]), "+r"((c)[1]), "+r"((c)[2]), "+r"((c)[3]) \
                 : "r"((a)[0]), "r"((a)[1]), "r"((a)[2]), "r"((a)[3]), \
                   "r"(b0), "r"(b1))

#define TERM(PK, W, PRD, CF)                         \
    {                                                \
        float E1 = fmaf((PK), (W), 1.f);             \
        (PRD) *= fmaxf(E1, ETH1);                    \
        (CF)  += fmasat_(E1, BIGF, NBIG);            \
    }

// ---------------- K0: quantize + norms + exact pos logits (one wave) --------
// 128 blocks x 1024 threads, 4 classes per block.
#define PREP_SMEM (32 * 512 * 4 + 32 * 4 + 4 * 64 * 4)

__global__ __launch_bounds__(1024)
void prep_kernel(const float* __restrict__ X) {
    extern __shared__ float psm[];
    float* sx  = psm;                       // [32][512]
    float* ssq = psm + 32 * 512;            // [32]
    float* sd  = ssq + 32;                  // [4][64]

    int tid  = threadIdx.x;
    int wid  = tid >> 5;                    // 0..31 (row within block)
    int lane = tid & 31;
    int cls  = wid >> 3;                    // 0..3 (class within block)
    int w8   = wid & 7;                     // row within class
    int row  = blockIdx.x * 32 + wid;

    if (blockIdx.x == 0 && tid == 0) {
        g_sumLoss = 0.f; g_cntTot = 0.f; g_ticket = 0u;
    }
    if (tid < 32) {
        int r = blockIdx.x * 32 + tid;
        g_rowS[r] = 0.f; g_rowNL[r] = 0.f; g_rowCnt[r] = 0.f;
    }

    const float4* xr = reinterpret_cast<const float4*>(X + (size_t)row * DIM);
    char4* q4 = reinterpret_cast<char4*>(g_Xq + (size_t)row * DIM);
    float* sxr = sx + wid * 512;
    float acc = 0.f;
#pragma unroll
    for (int l = 0; l < 4; l++) {
        int e4 = lane + 32 * l;
        float4 v = xr[e4];
        sxr[e4 * 4]     = v.x; sxr[e4 * 4 + 1] = v.y;
        sxr[e4 * 4 + 2] = v.z; sxr[e4 * 4 + 3] = v.w;
        acc = fmaf(v.x, v.x, acc); acc = fmaf(v.y, v.y, acc);
        acc = fmaf(v.z, v.z, acc); acc = fmaf(v.w, v.w, acc);
        float vv[4] = {v.x, v.y, v.z, v.w};
        int q[4];
#pragma unroll
        for (int u = 0; u < 4; u++) {
            float t = fminf(fmaxf(vv[u] * QINVS, -127.f), 127.f);
            q[u] = __float2int_rn(t);
        }
        q4[e4] = make_char4((char)q[0], (char)q[1], (char)q[2], (char)q[3]);
    }
#pragma unroll
    for (int o = 16; o; o >>= 1) acc += __shfl_xor_sync(0xffffffffu, acc, o);
    if (lane == 0) { g_sq[row] = acc; ssq[wid] = acc; }
    __syncthreads();

    // 28 unique pairs per class, 8 warps per class
    for (int pi = w8; pi < 28; pi += 8) {
        int a = 0, r = pi;
        while (r >= 7 - a) { r -= 7 - a; a++; }
        int b = a + 1 + r;
        const float* xa = sx + (cls * 8 + a) * 512;
        const float* xb = sx + (cls * 8 + b) * 512;
        float p = 0.f;
#pragma unroll
        for (int l = 0; l < 16; l++) {
            int e = lane + 32 * l;
            p = fmaf(xa[e], xb[e], p);
        }
#pragma unroll
        for (int o = 16; o; o >>= 1) p += __shfl_xor_sync(0xffffffffu, p, o);
        if (lane == 0) {
            float d2 = ssq[cls * 8 + a] + ssq[cls * 8 + b] - 2.f * p;
            float d  = sqrtf(fmaxf(d2, 1e-12f));
            sd[cls * 64 + a * 8 + b] = d;
            sd[cls * 64 + b * 8 + a] = d;
        }
    }
    __syncthreads();

    if (tid < 32) {
        int r    = tid & 7;
        int cls2 = tid >> 3;
        int rw   = blockIdx.x * 32 + tid;
        float pl = 0.f;
        int kidx = 0;
#pragma unroll
        for (int kk = 0; kk < 8; kk++) {
            if (kk == r) continue;
            float q = C4C * sd[cls2 * 64 + r * 8 + kk];
            g_P[(size_t)rw * 8 + kidx] = ex2f_(q);
            pl += ex2f_(fmaf(-10.f, q, C40C));
            kidx++;
        }
        g_P[(size_t)rw * 8 + 7] = pl;
    }
}

// ---------------- K1: fused IMMA GEMM + triplet epilogue (R12 verbatim) -----
#define TILE_B 16384
#define OFF_B0   0
#define OFF_B1   32768
#define OFF_B2   65536
#define OFF_SD   0                         // float [128][129] = 66048 B
#define OFF_PI   66048
#define OFF_PJ   70144
#define OFF_SA   74240
#define OFF_SB   74752
#define DSMEM_BYTES (1024 + 3 * 32768)     // 97 KB -> 2 CTAs/SM

__device__ __forceinline__ void load_stage_(u32 buf, int k0,
                                            const char* pa, const char* pb, int tid) {
    const char* ptr[2] = {pa, pb};
#pragma unroll
    for (int tl = 0; tl < 2; tl++) {
        const char* p = ptr[tl];
#pragma unroll
        for (int i = 0; i < 2; i++) {
            int cid = tid + i * 512;
            int r   = cid >> 3;
            int g   = cid & 7;
            u32 dst = buf + tl * TILE_B + SW128(r * 128 + g * 16);
            cp_async16_(dst, p + (size_t)r * DIM + k0 + g * 16);
        }
    }
    asm volatile("cp.async.commit_group;" ::: "memory");
}

__global__ __launch_bounds__(512, 2)
void mma_triplet_kernel() {
    extern __shared__ char dsm[];
    u32 raw  = smem_u32_(dsm);
    u32 base = (raw + 1023) & ~1023u;
    char* ebase = dsm + (base - raw);

    int t = blockIdx.x, bi = 0;
    while (t >= 32 - bi) { t -= 32 - bi; bi++; }
    int bj = bi + t;
    bool diag = (bi == bj);
    int tid  = threadIdx.x;
    int lane = tid & 31;
    int wid  = tid >> 5;
    int m0 = (wid & 3) * 32;
    int n0 = (wid >> 2) * 32;
    int ra = (lane & 7) + ((lane >> 3) & 1) * 8;
    int cb16 = ((lane >> 4) & 1) * 16;

    const char* pa = g_Xq + (size_t)bi * 128 * DIM;
    const char* pb = g_Xq + (size_t)bj * 128 * DIM;

    int acc[2][4][4];
#pragma unroll
    for (int mt = 0; mt < 2; mt++)
#pragma unroll
        for (int nt = 0; nt < 4; nt++)
#pragma unroll
            for (int v = 0; v < 4; v++) acc[mt][nt][v] = 0;

    load_stage_(base + OFF_B0, 0,   pa, pb, tid);   // G0
    load_stage_(base + OFF_B1, 128, pa, pb, tid);   // G1
    load_stage_(base + OFF_B2, 256, pa, pb, tid);   // G2

#define COMPUTE_STAGE(SBUF)                                                  \
    {                                                                        \
        u32 bA = (SBUF), bB = (SBUF) + TILE_B;                               \
        _Pragma("unroll")                                                    \
        for (int ks = 0; ks < 4; ks++) {                                     \
            int kb = ks * 32 + cb16;                                         \
            u32 Af[2][4], Bf[2][4];                                          \
            _Pragma("unroll")                                                \
            for (int mt = 0; mt < 2; mt++) {                                 \
                int r = m0 + mt * 16 + ra;                                   \
                LDX4(Af[mt], bA + SW128(r * 128 + kb));                      \
            }                                                                \
            _Pragma("unroll")                                                \
            for (int nb = 0; nb < 2; nb++) {                                 \
                int r = n0 + nb * 16 + ra;                                   \
                LDX4(Bf[nb], bB + SW128(r * 128 + kb));                      \
            }                                                                \
            _Pragma("unroll")                                                \
            for (int mt = 0; mt < 2; mt++)                                   \
                _Pragma("unroll")                                            \
                for (int nb = 0; nb < 2; nb++)                               \
                    _Pragma("unroll")                                        \
                    for (int h = 0; h < 2; h++)                              \
                        IMMA16832(acc[mt][nb * 2 + h], Af[mt],               \
                                  Bf[nb][h], Bf[nb][2 + h]);                 \
        }                                                                    \
    }

    waitg_<2>(); __syncthreads(); COMPUTE_STAGE(base + OFF_B0);
    __syncthreads();                                 // B0 free
    load_stage_(base + OFF_B0, 384, pa, pb, tid);    // G3 -> B0
    waitg_<2>(); __syncthreads(); COMPUTE_STAGE(base + OFF_B1);
    waitg_<1>(); __syncthreads(); COMPUTE_STAGE(base + OFF_B2);
    waitg_<0>(); __syncthreads(); COMPUTE_STAGE(base + OFF_B0);
#undef COMPUTE_STAGE
    __syncthreads();

    float* sD  = reinterpret_cast<float*>(ebase + OFF_SD);
    float* sPi = reinterpret_cast<float*>(ebase + OFF_PI);
    float* sPj = reinterpret_cast<float*>(ebase + OFF_PJ);
    float* ssA = reinterpret_cast<float*>(ebase + OFF_SA);
    float* ssB = reinterpret_cast<float*>(ebase + OFF_SB);
    const int row0 = bi * 128, col0 = bj * 128;

#pragma unroll
    for (int mt = 0; mt < 2; mt++)
#pragma unroll
        for (int nt = 0; nt < 4; nt++) {
            int rb = m0 + mt * 16 + (lane >> 2);
            int cbx = n0 + nt * 8 + (lane & 3) * 2;
            sD[rb * 129 + cbx]           = QS2 * (float)acc[mt][nt][0];
            sD[rb * 129 + cbx + 1]       = QS2 * (float)acc[mt][nt][1];
            sD[(rb + 8) * 129 + cbx]     = QS2 * (float)acc[mt][nt][2];
            sD[(rb + 8) * 129 + cbx + 1] = QS2 * (float)acc[mt][nt][3];
        }
    for (int idx = tid; idx < 1024; idx += 512) {
        sPi[idx] = g_P[(size_t)row0 * 8 + idx];
        sPj[idx] = g_P[(size_t)col0 * 8 + idx];
    }
    if (tid < 128) { ssA[tid] = g_sq[row0 + tid]; ssB[tid] = g_sq[col0 + tid]; }
    __syncthreads();

    // pass W
    for (int idx = tid; idx < 128 * 128; idx += 512) {
        int m = idx >> 7, c = idx & 127;
        float dot = sD[m * 129 + c];
        float d2  = ssA[m] + ssB[c] - 2.f * dot;
        float d   = sqrtf(fmaxf(d2, 1e-12f));
        float w   = ex2f_(-C4C * d);
        if (diag && ((m >> 3) == (c >> 3))) w = 0.f;
        sD[m * 129 + c] = w;
    }
    __syncthreads();

    // direction 1
    {
        int r = tid >> 2, q = tid & 3;
        float p[7];
#pragma unroll
        for (int k = 0; k < 7; k++) p[k] = sPi[r * 8 + k];
        const float* wr = sD + r * 129 + q * 32;
        int rot = 8 * q;
        float s = 0.f, nl = 0.f, cfA = 0.f, cfB = 0.f;
#pragma unroll 2
        for (int cc = 0; cc < 32; cc += 4) {
            float pA = 1.f, pB = 1.f, pC = 1.f, pD = 1.f;
#pragma unroll
            for (int u = 0; u < 4; u++) {
                float w  = wr[(cc + u + rot) & 31];
                float w2 = w * w, w4 = w2 * w2, w5 = w4 * w;
                nl = fmaf(K40C, w5 * w5, nl);
                TERM(p[0], w, pA, cfA); TERM(p[1], w, pB, cfB);
                TERM(p[2], w, pC, cfA); TERM(p[3], w, pD, cfB);
                TERM(p[4], w, pA, cfA); TERM(p[5], w, pB, cfB);
                TERM(p[6], w, pC, cfA);
            }
            s += (lg2f_(pA) + lg2f_(pB)) + (lg2f_(pC) + lg2f_(pD));
        }
        float cf = cfA + cfB;
        s  += __shfl_xor_sync(0xffffffffu, s, 1);
        nl += __shfl_xor_sync(0xffffffffu, nl, 1);
        cf += __shfl_xor_sync(0xffffffffu, cf, 1);
        s  += __shfl_xor_sync(0xffffffffu, s, 2);
        nl += __shfl_xor_sync(0xffffffffu, nl, 2);
        cf += __shfl_xor_sync(0xffffffffu, cf, 2);
        if (q == 0) {
            atomicAdd(&g_rowS[row0 + r], s);
            atomicAdd(&g_rowNL[row0 + r], nl);
            atomicAdd(&g_rowCnt[row0 + r], cf);
        }
    }

    // direction 2 (off-diag only)
    if (!diag) {
        int c = tid >> 2, q = tid & 3;
        float p[7];
#pragma unroll
        for (int k = 0; k < 7; k++) p[k] = sPj[c * 8 + k];
        const float* wc = sD + c;
        int rot = 8 * q;
        float s = 0.f, nl = 0.f, cfA = 0.f, cfB = 0.f;
#pragma unroll 2
        for (int mm = 0; mm < 32; mm += 4) {
            float pA = 1.f, pB = 1.f, pC = 1.f, pD = 1.f;
#pragma unroll
            for (int u = 0; u < 4; u++) {
                int mr = q * 32 + ((mm + u + rot) & 31);
                float w  = wc[mr * 129];
                float w2 = w * w, w4 = w2 * w2, w5 = w4 * w;
                nl = fmaf(K40C, w5 * w5, nl);
                TERM(p[0], w, pA, cfA); TERM(p[1], w, pB, cfB);
                TERM(p[2], w, pC, cfA); TERM(p[3], w, pD, cfB);
                TERM(p[4], w, pA, cfA); TERM(p[5], w, pB, cfB);
                TERM(p[6], w, pC, cfA);
            }
            s += (lg2f_(pA) + lg2f_(pB)) + (lg2f_(pC) + lg2f_(pD));
        }
        float cf = cfA + cfB;
        s  += __shfl_xor_sync(0xffffffffu, s, 1);
        nl += __shfl_xor_sync(0xffffffffu, nl, 1);
        cf += __shfl_xor_sync(0xffffffffu, cf, 1);
        s  += __shfl_xor_sync(0xffffffffu, s, 2);
        nl += __shfl_xor_sync(0xffffffffu, nl, 2);
        cf += __shfl_xor_sync(0xffffffffu, cf, 2);
        if (q == 0) {
            atomicAdd(&g_rowS[col0 + c], s);
            atomicAdd(&g_rowNL[col0 + c], nl);
            atomicAdd(&g_rowCnt[col0 + c], cf);
        }
    }
}

// ---------------- K2: finalize (applies max-floor correction) ---------------
__global__ __launch_bounds__(256)
void finalize_kernel(float* __restrict__ out) {
    __shared__ float sv[2][8];
    int tid = threadIdx.x;
    int lane = tid & 31, wrp = tid >> 5;
    int i = blockIdx.x * 256 + tid;

    float pl  = g_P[(size_t)i * 8 + 7];
    float S   = g_rowS[i];
    float NL  = g_rowNL[i];
    float CF  = g_rowCnt[i];
    float a_lr = 1.0f - pl / (pl + NL);
    float Sln = fmaf(LN2, S, -0.65f * (TOTN - CF));
    float rowval = a_lr * Sln / fmaxf(CF, 1.f);

    float v = rowval, cf = CF;
#pragma unroll
    for (int o = 16; o; o >>= 1) {
        v  += __shfl_xor_sync(0xffffffffu, v, o);
        cf += __shfl_xor_sync(0xffffffffu, cf, o);
    }
    if (lane == 0) { sv[0][wrp] = v; sv[1][wrp] = cf; }
    __syncthreads();
    if (tid == 0) {
        float V = 0.f, C = 0.f;
#pragma unroll
        for (int wq = 0; wq < 8; wq++) { V += sv[0][wq]; C += sv[1][wq]; }
        atomicAdd(&g_sumLoss, V);
        atomicAdd(&g_cntTot, C);
        __threadfence();
        u32 tk = atomicAdd(&g_ticket, 1u);
        if (tk == (NPTS / 256) - 1) {
            float sum = g_sumLoss;
            float ct  = g_cntTot;
            out[0] = (ct > 0.f) ? sum / ct : 0.f;
        }
    }
}

// ---------------- launch ----------------------------------------------------
extern "C" void kernel_launch(void* const* d_in, const int* in_sizes, int n_in,
                              void* d_out, int out_size) {
    const float* X = (const float*)d_in[0];
    float* out = (float*)d_out;

    cudaFuncSetAttribute(prep_kernel,
                         cudaFuncAttributeMaxDynamicSharedMemorySize, PREP_SMEM);
    prep_kernel<<<NPTS / 32, 1024, PREP_SMEM>>>(X);

    cudaFuncSetAttribute(mma_triplet_kernel,
                         cudaFuncAttributeMaxDynamicSharedMemorySize, DSMEM_BYTES);
    mma_triplet_kernel<<<NT, 512, DSMEM_BYTES>>>();

    finalize_kernel<<<NPTS / 256, 256>>>(out);
}